// round 4
// baseline (speedup 1.0000x reference)
#include <cuda_runtime.h>
#include <cuda_bf16.h>
#include <cstdint>
#include <math.h>

// ---------------------------------------------------------------------------
// Problem constants
// ---------------------------------------------------------------------------
#define NB    8          // batch
#define NW    1000       // windows per batch element
#define WS_   25         // window size
#define D0    256        // latent dim
#define H_    128        // hidden channels
#define NWIN  8000       // total windows
#define PADW  32         // padded rows per window (25 data + 7 zero)
#define ROWS_PAD (NWIN*PADW)   // 256000 padded rows

// ---------------------------------------------------------------------------
// Device scratch (static __device__ arrays -- no allocation)
// ---------------------------------------------------------------------------
__device__ __nv_bfloat16 g_w0p[7 * 256 * 128];   // [tap][ci][co]
__device__ __nv_bfloat16 g_w1p[5 * 128 * 128];
__device__ __nv_bfloat16 g_w2p[5 * 128 * 128];
__device__ __nv_bfloat16 g_act0[(size_t)ROWS_PAD * H_];  // padded (win,32,128)
__device__ __nv_bfloat16 g_act1[(size_t)ROWS_PAD * H_];
__device__ float         g_wscore[NWIN];

// ---------------------------------------------------------------------------
// Helpers
// ---------------------------------------------------------------------------
__device__ __forceinline__ float gelu_f(float x) {
    return 0.5f * x * (1.0f + erff(x * 0.70710678118654752f));
}

__device__ __forceinline__ uint32_t smem_u32(const void* p) {
    uint32_t a;
    asm("{ .reg .u64 t; cvta.to.shared.u64 t, %1; cvt.u32.u64 %0, t; }"
        : "=r"(a) : "l"(p));
    return a;
}

// ---------------------------------------------------------------------------
// Weight prep: transpose conv weights to [tap][ci][co] bf16
// ---------------------------------------------------------------------------
__global__ void prep_weights(const float* __restrict__ w0,
                             const float* __restrict__ w1,
                             const float* __restrict__ w2) {
    int idx = blockIdx.x * blockDim.x + threadIdx.x;
    if (idx < 7 * 256 * 128) {
        int co = idx & 127, ci = (idx >> 7) & 255, tap = idx >> 15;
        g_w0p[idx] = __float2bfloat16(w0[(co * 256 + ci) * 7 + tap]);
    }
    idx -= 7 * 256 * 128;
    if (idx >= 0 && idx < 5 * 128 * 128) {
        int co = idx & 127, ci = (idx >> 7) & 127, tap = idx >> 14;
        g_w1p[idx] = __float2bfloat16(w1[(co * 128 + ci) * 5 + tap]);
        g_w2p[idx] = __float2bfloat16(w2[(co * 128 + ci) * 5 + tap]);
    }
}

// ---------------------------------------------------------------------------
// Fused conv kernel: one CTA = 4 windows (M=128 padded rows), N=128 channels.
// K-loop: taps x C_IN, each tap is a shifted GEMM (window padding makes the
// shift safe). bf16 mma.sync m16n8k16, fp32 accum.
// WSEL: 0 = conv0 (input latents fp32, out g_act0)
//       1 = conv1 (in g_act0, out g_act1)
//       2 = conv2 (in g_act1) -- used with HEAD=true: pool + MLP head
// ---------------------------------------------------------------------------
template<int C_IN, int TAPS, int WSEL, bool HEAD>
__global__ void __launch_bounds__(256)
conv_kernel(const float* __restrict__ latents,
            const float* __restrict__ bias,
            const float* __restrict__ hw1, const float* __restrict__ hb1,
            const float* __restrict__ hw2, const float* __restrict__ hb2) {
    constexpr int ROWS_A = 144;          // 8 lead zeros + 128 + trailing pad
    constexpr int ROWB   = C_IN * 2;     // bytes per A row
    constexpr int NCH    = C_IN / 8;     // 16B chunks per A row
    constexpr int HALF   = TAPS / 2;

    extern __shared__ char smem[];
    char* sA_base = smem;                          // ROWS_A * ROWB bytes (swizzled)
    char* sB_base = smem + ROWS_A * ROWB;          // C_IN rows x 256B (swizzled)
    float* sFeat  = (float*)(smem + ROWS_A * ROWB + C_IN * 256); // HEAD only

    const int tid    = threadIdx.x;
    const int cta    = blockIdx.x;
    const int lane   = tid & 31;
    const int wid    = tid >> 5;
    const int warp_m = wid & 3;    // 4 along M (32 rows each = 1 window)
    const int warp_n = wid >> 2;   // 2 along N (64 cols each)

    const long Vbase = (long)cta * 128 - 8;

    // ---- Stage A tile into swizzled smem (bf16) -------------------------
    if constexpr (WSEL == 0) {
        for (int idx = tid; idx < ROWS_A * NCH; idx += 256) {
            int i = idx / NCH, c = idx - i * NCH;
            long V = Vbase + i;
            uint4 pk = make_uint4(0u, 0u, 0u, 0u);
            if (V >= 0 && V < (long)ROWS_PAD) {
                int dr = (int)(V & 31);
                if (dr < WS_) {
                    int win = (int)(V >> 5);
                    int b = win / NW, wi = win - b * NW;
                    const float* src =
                        latents + ((size_t)(b * 25000 + wi * WS_ + dr)) * D0 + c * 8;
                    float4 f0 = *(const float4*)src;
                    float4 f1 = *((const float4*)src + 1);
                    __nv_bfloat162 h0 = __floats2bfloat162_rn(f0.x, f0.y);
                    __nv_bfloat162 h1 = __floats2bfloat162_rn(f0.z, f0.w);
                    __nv_bfloat162 h2 = __floats2bfloat162_rn(f1.x, f1.y);
                    __nv_bfloat162 h3 = __floats2bfloat162_rn(f1.z, f1.w);
                    pk.x = *reinterpret_cast<uint32_t*>(&h0);
                    pk.y = *reinterpret_cast<uint32_t*>(&h1);
                    pk.z = *reinterpret_cast<uint32_t*>(&h2);
                    pk.w = *reinterpret_cast<uint32_t*>(&h3);
                }
            }
            *reinterpret_cast<uint4*>(sA_base + i * ROWB + (((c ^ (i & 7))) << 4)) = pk;
        }
    } else {
        const __nv_bfloat16* actin = (WSEL == 1) ? g_act0 : g_act1;
        for (int idx = tid; idx < ROWS_A * NCH; idx += 256) {
            int i = idx / NCH, c = idx - i * NCH;
            long V = Vbase + i;
            uint4 pk = make_uint4(0u, 0u, 0u, 0u);
            if (V >= 0 && V < (long)ROWS_PAD)
                pk = *reinterpret_cast<const uint4*>(actin + (size_t)V * H_ + c * 8);
            *reinterpret_cast<uint4*>(sA_base + i * ROWB + (((c ^ (i & 7))) << 4)) = pk;
        }
    }

    // ---- Mainloop: taps x k-steps ---------------------------------------
    float acc[2][8][4];
    #pragma unroll
    for (int tm = 0; tm < 2; ++tm)
        #pragma unroll
        for (int tn = 0; tn < 8; ++tn)
            #pragma unroll
            for (int j = 0; j < 4; ++j) acc[tm][tn][j] = 0.0f;

    const __nv_bfloat16* wp = (WSEL == 0) ? g_w0p : (WSEL == 1) ? g_w1p : g_w2p;
    const uint32_t sAu = smem_u32(sA_base);
    const uint32_t sBu = smem_u32(sB_base);

    for (int tap = 0; tap < TAPS; ++tap) {
        __syncthreads();  // also covers initial A staging
        // stage W[tap] (C_IN x 128 bf16) into swizzled smem
        for (int idx = tid; idx < C_IN * 16; idx += 256) {
            int ci = idx >> 4, cc = idx & 15;
            uint4 v = *reinterpret_cast<const uint4*>(
                wp + ((size_t)(tap * C_IN + ci)) * 128 + cc * 8);
            *reinterpret_cast<uint4*>(sB_base + ci * 256 + (((cc ^ (ci & 7))) << 4)) = v;
        }
        __syncthreads();

        const int rbase = 8 + tap - HALF + warp_m * 32;  // shifted A row base
        #pragma unroll 2
        for (int ks = 0; ks < C_IN / 16; ++ks) {
            uint32_t a[2][4];
            #pragma unroll
            for (int tm = 0; tm < 2; ++tm) {
                int row = rbase + tm * 16 + (lane & 15);
                int kch = ks * 2 + (lane >> 4);
                uint32_t addr = sAu + row * ROWB + (((kch ^ (row & 7))) << 4);
                asm volatile(
                    "ldmatrix.sync.aligned.m8n8.x4.shared.b16 {%0,%1,%2,%3}, [%4];"
                    : "=r"(a[tm][0]), "=r"(a[tm][1]), "=r"(a[tm][2]), "=r"(a[tm][3])
                    : "r"(addr));
            }
            uint32_t b[8][2];
            #pragma unroll
            for (int nb = 0; nb < 4; ++nb) {
                int krow = ks * 16 + (lane & 15);
                int nch  = warp_n * 8 + nb * 2 + (lane >> 4);
                uint32_t addr = sBu + krow * 256 + (((nch ^ (krow & 7))) << 4);
                asm volatile(
                    "ldmatrix.sync.aligned.m8n8.x4.trans.shared.b16 {%0,%1,%2,%3}, [%4];"
                    : "=r"(b[2 * nb][0]), "=r"(b[2 * nb][1]),
                      "=r"(b[2 * nb + 1][0]), "=r"(b[2 * nb + 1][1])
                    : "r"(addr));
            }
            #pragma unroll
            for (int tm = 0; tm < 2; ++tm)
                #pragma unroll
                for (int tn = 0; tn < 8; ++tn)
                    asm volatile(
                        "mma.sync.aligned.m16n8k16.row.col.f32.bf16.bf16.f32 "
                        "{%0,%1,%2,%3}, {%4,%5,%6,%7}, {%8,%9}, {%0,%1,%2,%3};"
                        : "+f"(acc[tm][tn][0]), "+f"(acc[tm][tn][1]),
                          "+f"(acc[tm][tn][2]), "+f"(acc[tm][tn][3])
                        : "r"(a[tm][0]), "r"(a[tm][1]), "r"(a[tm][2]), "r"(a[tm][3]),
                          "r"(b[tn][0]), "r"(b[tn][1]));
        }
    }

    // ---- Epilogue --------------------------------------------------------
    if constexpr (!HEAD) {
        __nv_bfloat16* actout = (WSEL == 0) ? g_act0 : g_act1;
        #pragma unroll
        for (int tm = 0; tm < 2; ++tm) {
            #pragma unroll
            for (int tn = 0; tn < 8; ++tn) {
                int col = warp_n * 64 + tn * 8 + (lane & 3) * 2;
                float b0 = bias[col], b1v = bias[col + 1];
                #pragma unroll
                for (int jh = 0; jh < 2; ++jh) {
                    int row = warp_m * 32 + tm * 16 + (lane >> 2) + jh * 8;
                    int dr = row & 31;
                    float v0 = 0.0f, v1 = 0.0f;
                    if (dr < WS_) {
                        v0 = gelu_f(acc[tm][tn][jh * 2 + 0] + b0);
                        v1 = gelu_f(acc[tm][tn][jh * 2 + 1] + b1v);
                    }
                    size_t R = (size_t)cta * 128 + row;
                    __nv_bfloat162 h = __floats2bfloat162_rn(v0, v1);
                    *reinterpret_cast<__nv_bfloat162*>(actout + R * H_ + col) = h;
                }
            }
        }
    } else {
        // pooling: each warp owns exactly one window (32 rows) x 64 cols half
        #pragma unroll
        for (int tn = 0; tn < 8; ++tn) {
            #pragma unroll
            for (int jl = 0; jl < 2; ++jl) {
                int col = warp_n * 64 + tn * 8 + (lane & 3) * 2 + jl;
                float bc = bias[col];
                float s = 0.0f;
                #pragma unroll
                for (int tm = 0; tm < 2; ++tm)
                    #pragma unroll
                    for (int jh = 0; jh < 2; ++jh) {
                        int row = warp_m * 32 + tm * 16 + (lane >> 2) + jh * 8;
                        if ((row & 31) < WS_)
                            s += gelu_f(acc[tm][tn][jh * 2 + jl] + bc);
                    }
                s += __shfl_xor_sync(0xffffffffu, s, 4);
                s += __shfl_xor_sync(0xffffffffu, s, 8);
                s += __shfl_xor_sync(0xffffffffu, s, 16);
                if ((lane >> 2) == 0)
                    sFeat[warp_m * 128 + col] = s * (1.0f / WS_);
            }
        }
        __syncthreads();
        if (wid < 4) {  // one warp per window: MLP head
            int win = wid;
            const float* f = sFeat + win * 128;
            float z = 0.0f;
            #pragma unroll
            for (int q = 0; q < 4; ++q) {
                int j = q * 32 + lane;
                float a = hb1[j];
                const float* wrow = hw1 + (size_t)j * 128;
                #pragma unroll 4
                for (int i = 0; i < 128; i += 4) {
                    float4 w = *reinterpret_cast<const float4*>(wrow + i);
                    a += f[i] * w.x + f[i + 1] * w.y + f[i + 2] * w.z + f[i + 3] * w.w;
                }
                z += gelu_f(a) * hw2[j];
            }
            #pragma unroll
            for (int o = 16; o > 0; o >>= 1)
                z += __shfl_xor_sync(0xffffffffu, z, o);
            if (lane == 0) {
                float zz = z + hb2[0];
                g_wscore[cta * 4 + win] = 5.0f / (1.0f + expf(-zz));
            }
        }
    }
}

// ---------------------------------------------------------------------------
// Finalize: mean over batch, threshold, write outputs
// ---------------------------------------------------------------------------
__global__ void finalize_kernel(float* __restrict__ out, int out_size) {
    int wi = blockIdx.x * blockDim.x + threadIdx.x;
    if (wi < NW) {
        float s = 0.0f;
        #pragma unroll
        for (int b = 0; b < NB; ++b) s += g_wscore[b * NW + wi];
        s *= (1.0f / NB);
        out[wi] = s;
        if (out_size >= 2 * NW)
            out[NW + wi] = (s < 3.5f) ? 1.0f : 0.0f;
    }
}

// ---------------------------------------------------------------------------
// Launch
// ---------------------------------------------------------------------------
extern "C" void kernel_launch(void* const* d_in, const int* in_sizes, int n_in,
                              void* d_out, int out_size) {
    const float* latents = (const float*)d_in[0];
    const float* c0w = (const float*)d_in[1];
    const float* c0b = (const float*)d_in[2];
    const float* c1w = (const float*)d_in[3];
    const float* c1b = (const float*)d_in[4];
    const float* c2w = (const float*)d_in[5];
    const float* c2b = (const float*)d_in[6];
    const float* hw1 = (const float*)d_in[7];
    const float* hb1 = (const float*)d_in[8];
    const float* hw2 = (const float*)d_in[9];
    const float* hb2 = (const float*)d_in[10];

    prep_weights<<<304, 1024>>>(c0w, c1w, c2w);

    {
        constexpr int SMEM = 144 * 512 + 256 * 256;  // 139264
        cudaFuncSetAttribute(conv_kernel<256, 7, 0, false>,
                             cudaFuncAttributeMaxDynamicSharedMemorySize, SMEM);
        conv_kernel<256, 7, 0, false><<<2000, 256, SMEM>>>(
            latents, c0b, nullptr, nullptr, nullptr, nullptr);
    }
    {
        constexpr int SMEM = 144 * 256 + 128 * 256;  // 69632
        cudaFuncSetAttribute(conv_kernel<128, 5, 1, false>,
                             cudaFuncAttributeMaxDynamicSharedMemorySize, SMEM);
        conv_kernel<128, 5, 1, false><<<2000, 256, SMEM>>>(
            nullptr, c1b, nullptr, nullptr, nullptr, nullptr);
    }
    {
        constexpr int SMEM = 144 * 256 + 128 * 256 + 4 * 128 * 4;  // 71680
        cudaFuncSetAttribute(conv_kernel<128, 5, 2, true>,
                             cudaFuncAttributeMaxDynamicSharedMemorySize, SMEM);
        conv_kernel<128, 5, 2, true><<<2000, 256, SMEM>>>(
            nullptr, c2b, hw1, hb1, hw2, hb2);
    }

    finalize_kernel<<<1, 1024>>>((float*)d_out, out_size);
}

// round 5
// speedup vs baseline: 1.1831x; 1.1831x over previous
#include <cuda_runtime.h>
#include <cuda_bf16.h>
#include <cstdint>
#include <math.h>

// ---------------------------------------------------------------------------
// Problem constants
// ---------------------------------------------------------------------------
#define NB    8          // batch
#define NW    1000       // windows per batch element
#define WS_   25         // window size
#define D0    256        // latent dim
#define H_    128        // hidden channels
#define NWIN  8000       // total windows
#define PADW  32         // padded rows per window (25 data + 7 zero)
#define ROWS_PAD (NWIN*PADW)   // 256000 padded rows

// ---------------------------------------------------------------------------
// Device scratch (static __device__ arrays -- no allocation)
// ---------------------------------------------------------------------------
__device__ __nv_bfloat16 g_w0p[7 * 256 * 128];   // [tap][ci][co]
__device__ __nv_bfloat16 g_w1p[5 * 128 * 128];
__device__ __nv_bfloat16 g_w2p[5 * 128 * 128];
__device__ __nv_bfloat16 g_act0[(size_t)ROWS_PAD * H_];  // padded (win,32,128)
__device__ __nv_bfloat16 g_act1[(size_t)ROWS_PAD * H_];
__device__ float         g_wscore[NWIN];

// ---------------------------------------------------------------------------
// Helpers
// ---------------------------------------------------------------------------
__device__ __forceinline__ float gelu_f(float x) {
    return 0.5f * x * (1.0f + erff(x * 0.70710678118654752f));
}

__device__ __forceinline__ uint32_t smem_u32(const void* p) {
    uint32_t a;
    asm("{ .reg .u64 t; cvta.to.shared.u64 t, %1; cvt.u32.u64 %0, t; }"
        : "=r"(a) : "l"(p));
    return a;
}

__device__ __forceinline__ void cp16(uint32_t dst, const void* src) {
    asm volatile("cp.async.cg.shared.global [%0], [%1], 16;"
                 :: "r"(dst), "l"(src));
}
__device__ __forceinline__ void cp16z(uint32_t dst, const void* src, int sz) {
    // copies sz bytes (0 or 16), zero-fills the rest of the 16B
    asm volatile("cp.async.cg.shared.global [%0], [%1], 16, %2;"
                 :: "r"(dst), "l"(src), "r"(sz));
}
__device__ __forceinline__ void cp_commit() {
    asm volatile("cp.async.commit_group;" ::: "memory");
}
__device__ __forceinline__ void cp_wait0() {
    asm volatile("cp.async.wait_group 0;" ::: "memory");
}

// ---------------------------------------------------------------------------
// Weight prep: transpose conv weights to [tap][ci][co] bf16
// ---------------------------------------------------------------------------
__global__ void prep_weights(const float* __restrict__ w0,
                             const float* __restrict__ w1,
                             const float* __restrict__ w2) {
    int idx = blockIdx.x * blockDim.x + threadIdx.x;
    if (idx < 7 * 256 * 128) {
        int co = idx & 127, ci = (idx >> 7) & 255, tap = idx >> 15;
        g_w0p[idx] = __float2bfloat16(w0[(co * 256 + ci) * 7 + tap]);
    }
    idx -= 7 * 256 * 128;
    if (idx >= 0 && idx < 5 * 128 * 128) {
        int co = idx & 127, ci = (idx >> 7) & 127, tap = idx >> 14;
        g_w1p[idx] = __float2bfloat16(w1[(co * 128 + ci) * 5 + tap]);
        g_w2p[idx] = __float2bfloat16(w2[(co * 128 + ci) * 5 + tap]);
    }
}

// ---------------------------------------------------------------------------
// Fused conv kernel: one CTA = 4 windows (M=128 padded rows), N=128 channels.
// K pipeline: stages of 128 input channels (taps x C_IN/128 stages), each
// stage's weight tile (128ci x 128co, 32KB) double-buffered via cp.async so
// staging of stage s+1 overlaps mma of stage s. One barrier per stage.
// WSEL: 0 = conv0 (input latents fp32, out g_act0)
//       1 = conv1 (in g_act0, out g_act1)
//       2 = conv2 (in g_act1) -- used with HEAD=true: pool + MLP head
// ---------------------------------------------------------------------------
template<int C_IN, int TAPS, int WSEL, bool HEAD>
__global__ void __launch_bounds__(256, 2)
conv_kernel(const float* __restrict__ latents,
            const float* __restrict__ bias,
            const float* __restrict__ hw1, const float* __restrict__ hb1,
            const float* __restrict__ hw2, const float* __restrict__ hb2) {
    constexpr int ROWS_A = 144;              // 8 lead zeros + 128 + trailing pad
    constexpr int ROWB   = C_IN * 2;         // bytes per A row
    constexpr int NCH    = C_IN / 8;         // 16B chunks per A row
    constexpr int HALF   = TAPS / 2;
    constexpr int SUBK   = C_IN / 128;       // 128-channel sub-stages per tap
    constexpr int NSTG   = TAPS * SUBK;      // total pipeline stages
    constexpr int BBUF   = 128 * 256;        // one B buffer: 128 rows x 256B

    extern __shared__ char smem[];
    char* sA_base = smem;                          // ROWS_A * ROWB (swizzled)
    char* sB_base = smem + ROWS_A * ROWB;          // 2 x BBUF (swizzled)
    float* sFeat  = (float*)(smem + ROWS_A * ROWB + 2 * BBUF); // HEAD only

    const int tid    = threadIdx.x;
    const int cta    = blockIdx.x;
    const int lane   = tid & 31;
    const int wid    = tid >> 5;
    const int warp_m = wid & 3;    // 4 along M (32 rows each = 1 window)
    const int warp_n = wid >> 2;   // 2 along N (64 cols each)

    const long Vbase = (long)cta * 128 - 8;
    const __nv_bfloat16* wp = (WSEL == 0) ? g_w0p : (WSEL == 1) ? g_w1p : g_w2p;
    const uint32_t sAu = smem_u32(sA_base);
    const uint32_t sBu = smem_u32(sB_base);

    // ---- Issue B stage 0 prefetch ---------------------------------------
    {
        const __nv_bfloat16* src = wp;  // stage 0 = first 128 ci rows
        #pragma unroll
        for (int idx = tid; idx < 128 * 16; idx += 256) {
            int ci = idx >> 4, cc = idx & 15;
            cp16(sBu + ci * 256 + (((cc ^ (ci & 7))) << 4),
                 src + (size_t)ci * 128 + cc * 8);
        }
        cp_commit();
    }

    // ---- Stage A tile into swizzled smem (bf16) -------------------------
    if constexpr (WSEL == 0) {
        for (int idx = tid; idx < ROWS_A * NCH; idx += 256) {
            int i = idx / NCH, c = idx - i * NCH;
            long V = Vbase + i;
            uint4 pk = make_uint4(0u, 0u, 0u, 0u);
            if (V >= 0 && V < (long)ROWS_PAD) {
                int dr = (int)(V & 31);
                if (dr < WS_) {
                    int win = (int)(V >> 5);
                    int b = win / NW, wi = win - b * NW;
                    const float* src =
                        latents + ((size_t)(b * 25000 + wi * WS_ + dr)) * D0 + c * 8;
                    float4 f0 = *(const float4*)src;
                    float4 f1 = *((const float4*)src + 1);
                    __nv_bfloat162 h0 = __floats2bfloat162_rn(f0.x, f0.y);
                    __nv_bfloat162 h1 = __floats2bfloat162_rn(f0.z, f0.w);
                    __nv_bfloat162 h2 = __floats2bfloat162_rn(f1.x, f1.y);
                    __nv_bfloat162 h3 = __floats2bfloat162_rn(f1.z, f1.w);
                    pk.x = *reinterpret_cast<uint32_t*>(&h0);
                    pk.y = *reinterpret_cast<uint32_t*>(&h1);
                    pk.z = *reinterpret_cast<uint32_t*>(&h2);
                    pk.w = *reinterpret_cast<uint32_t*>(&h3);
                }
            }
            *reinterpret_cast<uint4*>(sA_base + i * ROWB + (((c ^ (i & 7))) << 4)) = pk;
        }
    } else {
        const __nv_bfloat16* actin = (WSEL == 1) ? g_act0 : g_act1;
        for (int idx = tid; idx < ROWS_A * NCH; idx += 256) {
            int i = idx / NCH, c = idx - i * NCH;
            long V = Vbase + i;
            long Vc = V < 0 ? 0 : (V >= (long)ROWS_PAD ? (long)ROWS_PAD - 1 : V);
            int sz = (V >= 0 && V < (long)ROWS_PAD) ? 16 : 0;
            cp16z(sAu + i * ROWB + (((c ^ (i & 7))) << 4),
                  actin + (size_t)Vc * H_ + c * 8, sz);
        }
        cp_commit();
    }

    // ---- Pipelined mainloop over stages ---------------------------------
    float acc[2][8][4];
    #pragma unroll
    for (int tm = 0; tm < 2; ++tm)
        #pragma unroll
        for (int tn = 0; tn < 8; ++tn)
            #pragma unroll
            for (int j = 0; j < 4; ++j) acc[tm][tn][j] = 0.0f;

    int buf = 0;
    for (int s = 0; s < NSTG; ++s) {
        cp_wait0();
        __syncthreads();   // stage s B (+A on s=0) resident; buf^1 free

        if (s + 1 < NSTG) {  // prefetch stage s+1 into the other buffer
            const __nv_bfloat16* src = wp + (size_t)(s + 1) * 128 * 128;
            uint32_t base = sBu + (buf ^ 1) * BBUF;
            #pragma unroll
            for (int idx = tid; idx < 128 * 16; idx += 256) {
                int ci = idx >> 4, cc = idx & 15;
                cp16(base + ci * 256 + (((cc ^ (ci & 7))) << 4),
                     src + (size_t)ci * 128 + cc * 8);
            }
            cp_commit();
        }

        const int tap  = (SUBK == 1) ? s : (s / SUBK);
        const int koff = (SUBK == 1) ? 0 : ((s - tap * SUBK) * 16); // 8ch chunks
        const int rbase = 8 + tap - HALF + warp_m * 32;
        const uint32_t sBcur = sBu + buf * BBUF;

        #pragma unroll 2
        for (int ks = 0; ks < 8; ++ks) {
            uint32_t a[2][4];
            #pragma unroll
            for (int tm = 0; tm < 2; ++tm) {
                int row = rbase + tm * 16 + (lane & 15);
                int kch = koff + ks * 2 + (lane >> 4);
                uint32_t addr = sAu + row * ROWB + (((kch ^ (row & 7))) << 4);
                asm volatile(
                    "ldmatrix.sync.aligned.m8n8.x4.shared.b16 {%0,%1,%2,%3}, [%4];"
                    : "=r"(a[tm][0]), "=r"(a[tm][1]), "=r"(a[tm][2]), "=r"(a[tm][3])
                    : "r"(addr));
            }
            uint32_t b[8][2];
            #pragma unroll
            for (int nb = 0; nb < 4; ++nb) {
                int krow = ks * 16 + (lane & 15);
                int nch  = warp_n * 8 + nb * 2 + (lane >> 4);
                uint32_t addr = sBcur + krow * 256 + (((nch ^ (krow & 7))) << 4);
                asm volatile(
                    "ldmatrix.sync.aligned.m8n8.x4.trans.shared.b16 {%0,%1,%2,%3}, [%4];"
                    : "=r"(b[2 * nb][0]), "=r"(b[2 * nb][1]),
                      "=r"(b[2 * nb + 1][0]), "=r"(b[2 * nb + 1][1])
                    : "r"(addr));
            }
            #pragma unroll
            for (int tm = 0; tm < 2; ++tm)
                #pragma unroll
                for (int tn = 0; tn < 8; ++tn)
                    asm volatile(
                        "mma.sync.aligned.m16n8k16.row.col.f32.bf16.bf16.f32 "
                        "{%0,%1,%2,%3}, {%4,%5,%6,%7}, {%8,%9}, {%0,%1,%2,%3};"
                        : "+f"(acc[tm][tn][0]), "+f"(acc[tm][tn][1]),
                          "+f"(acc[tm][tn][2]), "+f"(acc[tm][tn][3])
                        : "r"(a[tm][0]), "r"(a[tm][1]), "r"(a[tm][2]), "r"(a[tm][3]),
                          "r"(b[tn][0]), "r"(b[tn][1]));
        }
        buf ^= 1;
    }

    // ---- Epilogue --------------------------------------------------------
    if constexpr (!HEAD) {
        __nv_bfloat16* actout = (WSEL == 0) ? g_act0 : g_act1;
        #pragma unroll
        for (int tm = 0; tm < 2; ++tm) {
            #pragma unroll
            for (int tn = 0; tn < 8; ++tn) {
                int col = warp_n * 64 + tn * 8 + (lane & 3) * 2;
                float b0 = bias[col], b1v = bias[col + 1];
                #pragma unroll
                for (int jh = 0; jh < 2; ++jh) {
                    int row = warp_m * 32 + tm * 16 + (lane >> 2) + jh * 8;
                    int dr = row & 31;
                    float v0 = 0.0f, v1 = 0.0f;
                    if (dr < WS_) {
                        v0 = gelu_f(acc[tm][tn][jh * 2 + 0] + b0);
                        v1 = gelu_f(acc[tm][tn][jh * 2 + 1] + b1v);
                    }
                    size_t R = (size_t)cta * 128 + row;
                    __nv_bfloat162 h = __floats2bfloat162_rn(v0, v1);
                    *reinterpret_cast<__nv_bfloat162*>(actout + R * H_ + col) = h;
                }
            }
        }
    } else {
        // pooling: each warp owns exactly one window (32 rows) x 64 cols half
        #pragma unroll
        for (int tn = 0; tn < 8; ++tn) {
            #pragma unroll
            for (int jl = 0; jl < 2; ++jl) {
                int col = warp_n * 64 + tn * 8 + (lane & 3) * 2 + jl;
                float bc = bias[col];
                float s = 0.0f;
                #pragma unroll
                for (int tm = 0; tm < 2; ++tm)
                    #pragma unroll
                    for (int jh = 0; jh < 2; ++jh) {
                        int row = warp_m * 32 + tm * 16 + (lane >> 2) + jh * 8;
                        if ((row & 31) < WS_)
                            s += gelu_f(acc[tm][tn][jh * 2 + jl] + bc);
                    }
                s += __shfl_xor_sync(0xffffffffu, s, 4);
                s += __shfl_xor_sync(0xffffffffu, s, 8);
                s += __shfl_xor_sync(0xffffffffu, s, 16);
                if ((lane >> 2) == 0)
                    sFeat[warp_m * 128 + col] = s * (1.0f / WS_);
            }
        }
        __syncthreads();
        if (wid < 4) {  // one warp per window: MLP head
            int win = wid;
            const float* f = sFeat + win * 128;
            float z = 0.0f;
            #pragma unroll
            for (int q = 0; q < 4; ++q) {
                int j = q * 32 + lane;
                float a = hb1[j];
                const float* wrow = hw1 + (size_t)j * 128;
                #pragma unroll 4
                for (int i = 0; i < 128; i += 4) {
                    float4 w = *reinterpret_cast<const float4*>(wrow + i);
                    a += f[i] * w.x + f[i + 1] * w.y + f[i + 2] * w.z + f[i + 3] * w.w;
                }
                z += gelu_f(a) * hw2[j];
            }
            #pragma unroll
            for (int o = 16; o > 0; o >>= 1)
                z += __shfl_xor_sync(0xffffffffu, z, o);
            if (lane == 0) {
                float zz = z + hb2[0];
                g_wscore[cta * 4 + win] = 5.0f / (1.0f + expf(-zz));
            }
        }
    }
}

// ---------------------------------------------------------------------------
// Finalize: mean over batch, threshold, write outputs
// ---------------------------------------------------------------------------
__global__ void finalize_kernel(float* __restrict__ out, int out_size) {
    int wi = blockIdx.x * blockDim.x + threadIdx.x;
    if (wi < NW) {
        float s = 0.0f;
        #pragma unroll
        for (int b = 0; b < NB; ++b) s += g_wscore[b * NW + wi];
        s *= (1.0f / NB);
        out[wi] = s;
        if (out_size >= 2 * NW)
            out[NW + wi] = (s < 3.5f) ? 1.0f : 0.0f;
    }
}

// ---------------------------------------------------------------------------
// Launch
// ---------------------------------------------------------------------------
extern "C" void kernel_launch(void* const* d_in, const int* in_sizes, int n_in,
                              void* d_out, int out_size) {
    const float* latents = (const float*)d_in[0];
    const float* c0w = (const float*)d_in[1];
    const float* c0b = (const float*)d_in[2];
    const float* c1w = (const float*)d_in[3];
    const float* c1b = (const float*)d_in[4];
    const float* c2w = (const float*)d_in[5];
    const float* c2b = (const float*)d_in[6];
    const float* hw1 = (const float*)d_in[7];
    const float* hb1 = (const float*)d_in[8];
    const float* hw2 = (const float*)d_in[9];
    const float* hb2 = (const float*)d_in[10];

    prep_weights<<<304, 1024>>>(c0w, c1w, c2w);

    {
        constexpr int SMEM = 144 * 512 + 2 * 128 * 256;  // 139264
        cudaFuncSetAttribute(conv_kernel<256, 7, 0, false>,
                             cudaFuncAttributeMaxDynamicSharedMemorySize, SMEM);
        conv_kernel<256, 7, 0, false><<<2000, 256, SMEM>>>(
            latents, c0b, nullptr, nullptr, nullptr, nullptr);
    }
    {
        constexpr int SMEM = 144 * 256 + 2 * 128 * 256;  // 102400
        cudaFuncSetAttribute(conv_kernel<128, 5, 1, false>,
                             cudaFuncAttributeMaxDynamicSharedMemorySize, SMEM);
        conv_kernel<128, 5, 1, false><<<2000, 256, SMEM>>>(
            nullptr, c1b, nullptr, nullptr, nullptr, nullptr);
    }
    {
        constexpr int SMEM = 144 * 256 + 2 * 128 * 256 + 4 * 128 * 4;  // 104448
        cudaFuncSetAttribute(conv_kernel<128, 5, 2, true>,
                             cudaFuncAttributeMaxDynamicSharedMemorySize, SMEM);
        conv_kernel<128, 5, 2, true><<<2000, 256, SMEM>>>(
            nullptr, c2b, hw1, hb1, hw2, hb2);
    }

    finalize_kernel<<<1, 1024>>>((float*)d_out, out_size);
}